// round 9
// baseline (speedup 1.0000x reference)
#include <cuda_runtime.h>
#include <cuda_bf16.h>
#include <cstdint>

// Problem: single-head causal attention
//   x [1024,256,512] fp32, Wq/Wk/Wv [512,64] fp32 -> out [1024,256,64] fp32
#define B_ 1024
#define T_ 256
#define C_ 512
#define H_ 64
#define M_ (B_ * T_)

// Scratch for Q, K, V.
__device__ float g_q[(size_t)M_ * H_];
__device__ float g_k[(size_t)M_ * H_];
__device__ float g_v[(size_t)M_ * H_];

// W in per-lane m16n8k16 B-fragment layout:
// index(o, half, ks, lane, j) = (((o*2+half)*32 + ks)*32 + lane)*16 + j
// where j = nt*2 + breg,  nt 0..7, breg 0..1.  value = pack(W[k][n], W[k+1][n])
// with n = nt*8 + lane>>2, k = ks*16 + (lane&3)*2 + breg*8.
__device__ __align__(16) uint32_t g_wfrag[3 * 2 * 32 * 32 * 16];

// ---------------------------------------------------------------------------
__device__ __forceinline__ void mma_bf16(float c[4], const uint32_t a[4],
                                         uint32_t b0, uint32_t b1) {
    asm volatile(
        "mma.sync.aligned.m16n8k16.row.col.f32.bf16.bf16.f32 "
        "{%0,%1,%2,%3}, {%4,%5,%6,%7}, {%8,%9}, {%0,%1,%2,%3};"
        : "+f"(c[0]), "+f"(c[1]), "+f"(c[2]), "+f"(c[3])
        : "r"(a[0]), "r"(a[1]), "r"(a[2]), "r"(a[3]), "r"(b0), "r"(b1));
}
__device__ __forceinline__ uint32_t pack_bf16x2(float a, float b) {
    __nv_bfloat16 ha = __float2bfloat16(a);
    __nv_bfloat16 hb = __float2bfloat16(b);
    return ((uint32_t)__bfloat16_as_ushort(hb) << 16) | __bfloat16_as_ushort(ha);
}
// Split a float2 into bf16 hi-pack and lo-pack.
__device__ __forceinline__ void split2(float2 v, uint32_t& hi, uint32_t& lo) {
    __nv_bfloat16 h0 = __float2bfloat16(v.x);
    __nv_bfloat16 h1 = __float2bfloat16(v.y);
    hi = ((uint32_t)__bfloat16_as_ushort(h1) << 16) | __bfloat16_as_ushort(h0);
    lo = pack_bf16x2(v.x - __bfloat162float(h0), v.y - __bfloat162float(h1));
}

// ---------------------------------------------------------------------------
// Kernel 0: one-time W convert into fragment layout. 98304 uint32 outputs.
// ---------------------------------------------------------------------------
__global__ void wconv_kernel(const float* __restrict__ Wq,
                             const float* __restrict__ Wk,
                             const float* __restrict__ Wv)
{
    const int id = blockIdx.x * 256 + threadIdx.x;        // < 98304
    const int br   = id & 1;
    const int nt   = (id >> 1) & 7;
    const int lane = (id >> 4) & 31;
    const int ks   = (id >> 9) & 31;
    const int half = (id >> 14) & 1;
    const int o    = id >> 15;

    const int n = nt * 8 + (lane >> 2);
    const int k = ks * 16 + (lane & 3) * 2 + br * 8;
    const float* W = (o == 0) ? Wq : (o == 1) ? Wk : Wv;
    const float v0 = W[(size_t)k * H_ + n];
    const float v1 = W[(size_t)(k + 1) * H_ + n];
    uint32_t hi, lo;
    split2(make_float2(v0, v1), hi, lo);
    g_wfrag[id] = half ? lo : hi;
}

// ---------------------------------------------------------------------------
// Kernel 1: QKV projection, register-direct HMMA (no smem, no syncs).
// 12 warps: warp w -> output o=w>>2, rows m0=(w&3)*32 (2 m16 tiles).
// Per k16 step: 8 LDG.64 (A from X, convert in regs) + 8 LDG.128 (B frags)
// + 48 mma (3-pass hi/lo split).
// ---------------------------------------------------------------------------
__global__ __launch_bounds__(384, 1)
void proj_kernel(const float* __restrict__ X)
{
    const int tid  = threadIdx.x;
    const int lane = tid & 31;
    const int wid  = tid >> 5;
    const int row0 = blockIdx.x * 128;
    const int o    = wid >> 2;
    const int m0   = (wid & 3) * 32;

    float acc[2][8][4];
    #pragma unroll
    for (int mt = 0; mt < 2; ++mt)
        #pragma unroll
        for (int nt = 0; nt < 8; ++nt)
            #pragma unroll
            for (int i = 0; i < 4; ++i) acc[mt][nt][i] = 0.f;

    // A row pointers for this lane: rows r, r+8, r+16, r+24.
    const int rbase = row0 + m0 + (lane >> 2);
    const float* xr = X + (size_t)rbase * C_ + (lane & 3) * 2;

    // B fragment base (uint4 granularity): 4 uint4 per (half, ks).
    const uint4* bhp = reinterpret_cast<const uint4*>(g_wfrag) +
                       (size_t)(o * 2 + 0) * 4096 + (size_t)lane * 4;
    const uint4* blp = reinterpret_cast<const uint4*>(g_wfrag) +
                       (size_t)(o * 2 + 1) * 4096 + (size_t)lane * 4;

    for (int ks = 0; ks < 32; ++ks) {
        const int kc = ks * 16;

        // ---- A fragments: load fp32, split to bf16 hi/lo in regs ----
        float2 f00 = *reinterpret_cast<const float2*>(xr + 0 * C_ + kc);
        float2 f10 = *reinterpret_cast<const float2*>(xr + 8 * C_ + kc);
        float2 f01 = *reinterpret_cast<const float2*>(xr + 0 * C_ + kc + 8);
        float2 f11 = *reinterpret_cast<const float2*>(xr + 8 * C_ + kc + 8);
        float2 f20 = *reinterpret_cast<const float2*>(xr + 16 * C_ + kc);
        float2 f30 = *reinterpret_cast<const float2*>(xr + 24 * C_ + kc);
        float2 f21 = *reinterpret_cast<const float2*>(xr + 16 * C_ + kc + 8);
        float2 f31 = *reinterpret_cast<const float2*>(xr + 24 * C_ + kc + 8);

        // ---- B fragments: 16 uint32 per half (nt*2+breg) ----
        uint4 bh4[4], bl4[4];
        #pragma unroll
        for (int j = 0; j < 4; ++j) bh4[j] = bhp[(size_t)ks * 128 + j];
        #pragma unroll
        for (int j = 0; j < 4; ++j) bl4[j] = blp[(size_t)ks * 128 + j];
        const uint32_t* bh = reinterpret_cast<const uint32_t*>(bh4);
        const uint32_t* bl = reinterpret_cast<const uint32_t*>(bl4);

        uint32_t ah[2][4], al[2][4];
        split2(f00, ah[0][0], al[0][0]);
        split2(f10, ah[0][1], al[0][1]);
        split2(f01, ah[0][2], al[0][2]);
        split2(f11, ah[0][3], al[0][3]);
        split2(f20, ah[1][0], al[1][0]);
        split2(f30, ah[1][1], al[1][1]);
        split2(f21, ah[1][2], al[1][2]);
        split2(f31, ah[1][3], al[1][3]);

        // ---- 3 passes: hi*hi, hi*lo, lo*hi ----
        #pragma unroll
        for (int mt = 0; mt < 2; ++mt)
            #pragma unroll
            for (int nt = 0; nt < 8; ++nt)
                mma_bf16(acc[mt][nt], ah[mt], bh[nt * 2], bh[nt * 2 + 1]);
        #pragma unroll
        for (int mt = 0; mt < 2; ++mt)
            #pragma unroll
            for (int nt = 0; nt < 8; ++nt)
                mma_bf16(acc[mt][nt], ah[mt], bl[nt * 2], bl[nt * 2 + 1]);
        #pragma unroll
        for (int mt = 0; mt < 2; ++mt)
            #pragma unroll
            for (int nt = 0; nt < 8; ++nt)
                mma_bf16(acc[mt][nt], al[mt], bh[nt * 2], bh[nt * 2 + 1]);
    }

    // ---- Epilogue ----
    const int g  = lane >> 2;
    const int tg = lane & 3;
    float* dst = (o == 0) ? g_q : (o == 1) ? g_k : g_v;
    #pragma unroll
    for (int mt = 0; mt < 2; ++mt) {
        #pragma unroll
        for (int nt = 0; nt < 8; ++nt) {
            const int row = row0 + m0 + mt * 16 + g;
            const int col = nt * 8 + tg * 2;
            float2 lo2 = make_float2(acc[mt][nt][0], acc[mt][nt][1]);
            float2 hi2 = make_float2(acc[mt][nt][2], acc[mt][nt][3]);
            *reinterpret_cast<float2*>(&dst[(size_t)row * H_ + col])       = lo2;
            *reinterpret_cast<float2*>(&dst[(size_t)(row + 8) * H_ + col]) = hi2;
        }
    }
}

// ---------------------------------------------------------------------------
// Kernel 2: causal attention. One CTA (512 threads) per batch; K,V fp32 in
// 128 KB smem. TWO threads per query row: even lane-half owns 16B chunks
// {0,2,4,...}, odd owns {1,3,5,...} (conflict-free broadcast pairs).
// Dot product combined via shfl_xor(.,1). Row blocks permuted for per-SMSP
// causal balance.
// ---------------------------------------------------------------------------
__global__ __launch_bounds__(512) void attn_kernel(float* __restrict__ out)
{
    extern __shared__ float sm[];
    float* Ks = sm;                 // [256][64]
    float* Vs = sm + T_ * H_;

    const int b   = blockIdx.x;
    const int tid = threadIdx.x;

    {
        const float4* Kb = reinterpret_cast<const float4*>(g_k + (size_t)b * T_ * H_);
        const float4* Vb = reinterpret_cast<const float4*>(g_v + (size_t)b * T_ * H_);
        float4* Ks4 = reinterpret_cast<float4*>(Ks);
        float4* Vs4 = reinterpret_cast<float4*>(Vs);
        #pragma unroll
        for (int i = tid; i < T_ * H_ / 4; i += 512) {
            Ks4[i] = Kb[i];
            Vs4[i] = Vb[i];
        }
    }
    __syncthreads();

    const int wid  = tid >> 5;
    const int lane = tid & 31;
    // per-SMSP balanced row-block permutation
    const int kk = wid >> 2, ss = wid & 3;
    const int rb = kk * 4 + ((kk & 1) ? (3 - ss) : ss);
    const int t  = rb * 16 + (lane >> 1);
    const int h  = lane & 1;          // which interleaved half of the 64 dims

    // This thread's 8 chunks: float4 indices {2i + h}, i = 0..7.
    float q[32];
    {
        const float4* qp = reinterpret_cast<const float4*>(
            g_q + ((size_t)b * T_ + t) * H_);
        #pragma unroll
        for (int i = 0; i < 8; ++i) {
            float4 v = qp[2 * i + h];
            q[4 * i + 0] = v.x * 0.125f;
            q[4 * i + 1] = v.y * 0.125f;
            q[4 * i + 2] = v.z * 0.125f;
            q[4 * i + 3] = v.w * 0.125f;
        }
    }

    float acc[32];
    #pragma unroll
    for (int j = 0; j < 32; ++j) acc[j] = 0.f;
    float m = -1e30f;
    float l = 0.f;

    for (int s = 0; s <= t; ++s) {
        const float4* k4 = reinterpret_cast<const float4*>(&Ks[s * H_]);
        float w0 = 0.f, w1 = 0.f, w2 = 0.f, w3 = 0.f;
        #pragma unroll
        for (int i = 0; i < 8; ++i) {
            float4 kv = k4[2 * i + h];
            w0 += q[4 * i + 0] * kv.x;
            w1 += q[4 * i + 1] * kv.y;
            w2 += q[4 * i + 2] * kv.z;
            w3 += q[4 * i + 3] * kv.w;
        }
        float wp = (w0 + w1) + (w2 + w3);
        const float w = wp + __shfl_xor_sync(0xFFFFFFFFu, wp, 1);

        const float4* v4 = reinterpret_cast<const float4*>(&Vs[s * H_]);
        if (w <= m) {
            const float p = __expf(w - m);
            l += p;
            #pragma unroll
            for (int i = 0; i < 8; ++i) {
                float4 vv = v4[2 * i + h];
                acc[4 * i + 0] += p * vv.x;
                acc[4 * i + 1] += p * vv.y;
                acc[4 * i + 2] += p * vv.z;
                acc[4 * i + 3] += p * vv.w;
            }
        } else {
            const float c = __expf(m - w);
            l = l * c + 1.f;
            #pragma unroll
            for (int i = 0; i < 8; ++i) {
                float4 vv = v4[2 * i + h];
                acc[4 * i + 0] = acc[4 * i + 0] * c + vv.x;
                acc[4 * i + 1] = acc[4 * i + 1] * c + vv.y;
                acc[4 * i + 2] = acc[4 * i + 2] * c + vv.z;
                acc[4 * i + 3] = acc[4 * i + 3] * c + vv.w;
            }
            m = w;
        }
    }

    const float inv = 1.f / l;
    float4* op = reinterpret_cast<float4*>(out + ((size_t)b * T_ + t) * H_);
    #pragma unroll
    for (int i = 0; i < 8; ++i) {
        float4 v;
        v.x = acc[4 * i + 0] * inv;
        v.y = acc[4 * i + 1] * inv;
        v.z = acc[4 * i + 2] * inv;
        v.w = acc[4 * i + 3] * inv;
        op[2 * i + h] = v;
    }
}

// ---------------------------------------------------------------------------
extern "C" void kernel_launch(void* const* d_in, const int* in_sizes, int n_in,
                              void* d_out, int out_size)
{
    const float* x  = (const float*)d_in[0];
    const float* Wq = (const float*)d_in[1];
    const float* Wk = (const float*)d_in[2];
    const float* Wv = (const float*)d_in[3];
    float* out = (float*)d_out;

    cudaFuncSetAttribute(attn_kernel,
                         cudaFuncAttributeMaxDynamicSharedMemorySize,
                         2 * T_ * H_ * (int)sizeof(float));

    wconv_kernel<<<384, 256>>>(Wq, Wk, Wv);
    proj_kernel<<<M_ / 128, 384>>>(x);
    attn_kernel<<<B_, 512, 2 * T_ * H_ * (int)sizeof(float)>>>(out);
}

// round 12
// speedup vs baseline: 1.6886x; 1.6886x over previous
#include <cuda_runtime.h>
#include <cuda_bf16.h>
#include <cstdint>

// Problem: single-head causal attention
//   x [1024,256,512] fp32, Wq/Wk/Wv [512,64] fp32 -> out [1024,256,64] fp32
#define B_ 1024
#define T_ 256
#define C_ 512
#define H_ 64
#define M_ (B_ * T_)

// Scratch for Q, K, V.
__device__ float g_q[(size_t)M_ * H_];
__device__ float g_k[(size_t)M_ * H_];
__device__ float g_v[(size_t)M_ * H_];

// Pre-converted, transposed weights: [o][n=64][k=512] bf16, hi/lo split.
__device__ __align__(16) __nv_bfloat16 g_wt_hi[3 * H_ * C_];
__device__ __align__(16) __nv_bfloat16 g_wt_lo[3 * H_ * C_];

// ---------------------------------------------------------------------------
// PTX helpers (sm_80-class features only: ldmatrix, mma.sync, cp.async).
// ---------------------------------------------------------------------------
__device__ __forceinline__ uint32_t smem_u32(const void* p) {
    uint32_t a;
    asm("{ .reg .u64 t; cvta.to.shared.u64 t, %1; cvt.u32.u64 %0, t; }"
        : "=r"(a) : "l"(p));
    return a;
}
__device__ __forceinline__ void ldsm_x4(uint32_t addr, uint32_t r[4]) {
    asm volatile("ldmatrix.sync.aligned.m8n8.x4.shared.b16 {%0,%1,%2,%3}, [%4];"
                 : "=r"(r[0]), "=r"(r[1]), "=r"(r[2]), "=r"(r[3]) : "r"(addr));
}
__device__ __forceinline__ void mma_bf16(float c[4], const uint32_t a[4],
                                         uint32_t b0, uint32_t b1) {
    asm volatile(
        "mma.sync.aligned.m16n8k16.row.col.f32.bf16.bf16.f32 "
        "{%0,%1,%2,%3}, {%4,%5,%6,%7}, {%8,%9}, {%0,%1,%2,%3};"
        : "+f"(c[0]), "+f"(c[1]), "+f"(c[2]), "+f"(c[3])
        : "r"(a[0]), "r"(a[1]), "r"(a[2]), "r"(a[3]), "r"(b0), "r"(b1));
}
__device__ __forceinline__ void cp16(uint32_t dst, const void* src) {
    asm volatile("cp.async.ca.shared.global [%0], [%1], 16;"
                 :: "r"(dst), "l"(src) : "memory");
}
#define CP_COMMIT() asm volatile("cp.async.commit_group;" ::: "memory")
#define CP_WAIT0()  asm volatile("cp.async.wait_group 0;" ::: "memory")

__device__ __forceinline__ uint32_t pack_bf16x2(float a, float b) {
    __nv_bfloat16 ha = __float2bfloat16(a);
    __nv_bfloat16 hb = __float2bfloat16(b);
    return ((uint32_t)__bfloat16_as_ushort(hb) << 16) | __bfloat16_as_ushort(ha);
}
__device__ __forceinline__ void split2(float2 v, uint32_t& hi, uint32_t& lo) {
    __nv_bfloat16 h0 = __float2bfloat16(v.x);
    __nv_bfloat16 h1 = __float2bfloat16(v.y);
    hi = ((uint32_t)__bfloat16_as_ushort(h1) << 16) | __bfloat16_as_ushort(h0);
    lo = pack_bf16x2(v.x - __bfloat162float(h0), v.y - __bfloat162float(h1));
}

// ---------------------------------------------------------------------------
// Kernel 0: one-time W convert+transpose+split (k fastest -> coalesced).
// ---------------------------------------------------------------------------
__global__ void wconv_kernel(const float* __restrict__ Wq,
                             const float* __restrict__ Wk,
                             const float* __restrict__ Wv)
{
    const int id = blockIdx.x * 256 + threadIdx.x;   // < 98304
    const int o   = id >> 15;
    const int rem = id & 32767;
    const int n   = rem >> 9;
    const int k   = rem & 511;
    const float* W = (o == 0) ? Wq : (o == 1) ? Wk : Wv;
    const float v = W[(size_t)k * H_ + n];
    const __nv_bfloat16 h = __float2bfloat16(v);
    g_wt_hi[id] = h;
    g_wt_lo[id] = __float2bfloat16(v - __bfloat162float(h));
}

// ---------------------------------------------------------------------------
// Kernel 1: QKV projection on HMMA, software-pipelined:
//   - B tiles: cp.async double buffer, issued one chunk ahead (latency hidden
//     under previous chunk's MMA phase)
//   - X chunk: prefetched into registers during MMA phase; only split+STS on
//     the critical path
// 12 warps: warp w -> output (w>>2), rows (w&3)*32. ROWB=144 pad (no LDSM
// conflicts).
// ---------------------------------------------------------------------------
#define ROWB    144
#define SM_A_HI 0                         // [128][ROWB] = 18432 B
#define SM_A_LO 18432
#define SM_B    36864                     // 2 bufs x 6 tiles x 9216 B
#define BBUF    55296                     // 6 * 9216
#define PROJ_SMEM (36864 + 2 * 55296)     // 147456 B

__global__ __launch_bounds__(384, 1)
void proj_kernel(const float* __restrict__ X)
{
    extern __shared__ __align__(16) char smem[];
    const uint32_t sb = smem_u32(smem);
    const int tid  = threadIdx.x;
    const int lane = tid & 31;
    const int wid  = tid >> 5;
    const int row0 = blockIdx.x * 128;

    const int o  = wid >> 2;
    const int m0 = (wid & 3) * 32;

    float acc[2][8][4];
    #pragma unroll
    for (int mt = 0; mt < 2; ++mt)
        #pragma unroll
        for (int nt = 0; nt < 8; ++nt)
            #pragma unroll
            for (int i = 0; i < 4; ++i) acc[mt][nt][i] = 0.f;

    // ldmatrix lane mapping
    const int lr = lane & 7;
    const int ls = lane >> 3;
    const uint32_t kpart = (uint32_t)((ls >> 1) << 4);   // bytes: +16 for mats 2,3
    uint32_t a_off[2], b_off[4];
    #pragma unroll
    for (int mt = 0; mt < 2; ++mt)
        a_off[mt] = (uint32_t)(m0 + mt * 16 + lr + ((ls & 1) << 3)) * ROWB + kpart;
    #pragma unroll
    for (int np = 0; np < 4; ++np)
        b_off[np] = (uint32_t)(np * 16 + lr + ((ls & 1) << 3)) * ROWB + kpart;

    const uint32_t aHi = sb + SM_A_HI;
    const uint32_t aLo = sb + SM_A_LO;

    // ---- prefetch helpers ----
    // X chunk -> registers (<= 6 float4 / thread)
    float4 xa[6];
    auto ldg_x = [&](int k0) {
        #pragma unroll
        for (int it = 0; it < 6; ++it) {
            const int id = tid + it * 384;
            if (id < 2048) {
                const int r  = id >> 4;
                const int c4 = (id & 15) * 4;
                xa[it] = *reinterpret_cast<const float4*>(
                    &X[(size_t)(row0 + r) * C_ + k0 + c4]);
            }
        }
    };
    // B tiles -> smem buffer via cp.async (8 x 16B / thread)
    auto cp_b = [&](int k0, int buf) {
        const uint32_t dst0 = sb + SM_B + (uint32_t)buf * BBUF;
        #pragma unroll
        for (int it = 0; it < 8; ++it) {
            const int id  = tid + it * 384;          // < 3072
            const int o2  = id >> 9;
            const int rem = id & 511;
            const int r   = rem >> 3;
            const int j   = rem & 7;
            const __nv_bfloat16* src = ((o2 & 1) ? g_wt_lo : g_wt_hi) +
                (size_t)(o2 >> 1) * 32768 + (size_t)r * 512 + k0 + j * 8;
            cp16(dst0 + (uint32_t)o2 * 9216 + (uint32_t)r * ROWB + j * 16, src);
        }
        CP_COMMIT();
    };

    // ---- prologue: chunk 0 in flight ----
    ldg_x(0);
    cp_b(0, 0);

    for (int ch = 0; ch < 8; ++ch) {
        CP_WAIT0();            // B(ch) resident
        __syncthreads();       // MMA(ch-1) done reading A buffer

        // split X(ch) regs -> A bf16 smem
        #pragma unroll
        for (int it = 0; it < 6; ++it) {
            const int id = tid + it * 384;
            if (id < 2048) {
                const int r  = id >> 4;
                const int c4 = (id & 15) * 4;
                const uint32_t d = (uint32_t)r * ROWB + (uint32_t)c4 * 2;
                uint32_t h01, l01, h23, l23;
                split2(make_float2(xa[it].x, xa[it].y), h01, l01);
                split2(make_float2(xa[it].z, xa[it].w), h23, l23);
                *reinterpret_cast<uint32_t*>(smem + SM_A_HI + d)     = h01;
                *reinterpret_cast<uint32_t*>(smem + SM_A_HI + d + 4) = h23;
                *reinterpret_cast<uint32_t*>(smem + SM_A_LO + d)     = l01;
                *reinterpret_cast<uint32_t*>(smem + SM_A_LO + d + 4) = l23;
            }
        }
        // prefetch chunk ch+1 (latency hidden under MMA below)
        if (ch < 7) {
            ldg_x((ch + 1) * 64);
            cp_b((ch + 1) * 64, (ch + 1) & 1);
        }
        __syncthreads();       // A(ch) visible

        const uint32_t bHi = sb + SM_B + (uint32_t)(ch & 1) * BBUF +
                             (uint32_t)(o * 2 + 0) * 9216;
        const uint32_t bLo = bHi + 9216;

        #pragma unroll
        for (int s = 0; s < 4; ++s) {
            const uint32_t kb = (uint32_t)s * 32;
            uint32_t ah[2][4], al[2][4], bh[4][4], bl[4][4];
            ldsm_x4(aHi + a_off[0] + kb, ah[0]);
            ldsm_x4(aHi + a_off[1] + kb, ah[1]);
            ldsm_x4(aLo + a_off[0] + kb, al[0]);
            ldsm_x4(aLo + a_off[1] + kb, al[1]);
            #pragma unroll
            for (int np = 0; np < 4; ++np) {
                ldsm_x4(bHi + b_off[np] + kb, bh[np]);
                ldsm_x4(bLo + b_off[np] + kb, bl[np]);
            }
            #pragma unroll
            for (int mt = 0; mt < 2; ++mt)
                #pragma unroll
                for (int nt = 0; nt < 8; ++nt)
                    mma_bf16(acc[mt][nt], ah[mt],
                             bh[nt >> 1][nt & 1], bh[nt >> 1][2 + (nt & 1)]);
            #pragma unroll
            for (int mt = 0; mt < 2; ++mt)
                #pragma unroll
                for (int nt = 0; nt < 8; ++nt)
                    mma_bf16(acc[mt][nt], ah[mt],
                             bl[nt >> 1][nt & 1], bl[nt >> 1][2 + (nt & 1)]);
            #pragma unroll
            for (int mt = 0; mt < 2; ++mt)
                #pragma unroll
                for (int nt = 0; nt < 8; ++nt)
                    mma_bf16(acc[mt][nt], al[mt],
                             bh[nt >> 1][nt & 1], bh[nt >> 1][2 + (nt & 1)]);
        }
    }

    // ---- Epilogue ----
    const int g  = lane >> 2;
    const int tg = lane & 3;
    float* dst = (o == 0) ? g_q : (o == 1) ? g_k : g_v;
    #pragma unroll
    for (int mt = 0; mt < 2; ++mt) {
        #pragma unroll
        for (int nt = 0; nt < 8; ++nt) {
            const int row = row0 + m0 + mt * 16 + g;
            const int col = nt * 8 + tg * 2;
            float2 lo2 = make_float2(acc[mt][nt][0], acc[mt][nt][1]);
            float2 hi2 = make_float2(acc[mt][nt][2], acc[mt][nt][3]);
            *reinterpret_cast<float2*>(&dst[(size_t)row * H_ + col])       = lo2;
            *reinterpret_cast<float2*>(&dst[(size_t)(row + 8) * H_ + col]) = hi2;
        }
    }
}

// ---------------------------------------------------------------------------
// Kernel 2: causal attention (R7-proven version): one block (256 thr) per
// batch, K,V in 128 KB smem, one thread per query row, online softmax,
// SMSP-balanced warp mapping.
// ---------------------------------------------------------------------------
__global__ __launch_bounds__(256) void attn_kernel(float* __restrict__ out)
{
    extern __shared__ float sm[];
    float* Ks = sm;
    float* Vs = sm + T_ * H_;

    const int b   = blockIdx.x;
    const int tid = threadIdx.x;

    {
        const float4* Kb = reinterpret_cast<const float4*>(g_k + (size_t)b * T_ * H_);
        const float4* Vb = reinterpret_cast<const float4*>(g_v + (size_t)b * T_ * H_);
        float4* Ks4 = reinterpret_cast<float4*>(Ks);
        float4* Vs4 = reinterpret_cast<float4*>(Vs);
        #pragma unroll
        for (int i = tid; i < T_ * H_ / 4; i += 256) {
            Ks4[i] = Kb[i];
            Vs4[i] = Vb[i];
        }
    }
    __syncthreads();

    const int wid  = tid >> 5;
    const int lane = tid & 31;
    const int wb   = (wid < 4) ? wid : (11 - wid);
    const int t    = wb * 32 + lane;

    float q[H_];
    {
        const float* qp = g_q + ((size_t)b * T_ + t) * H_;
        #pragma unroll
        for (int j = 0; j < H_; j += 4) {
            float4 v = *reinterpret_cast<const float4*>(&qp[j]);
            q[j + 0] = v.x * 0.125f;
            q[j + 1] = v.y * 0.125f;
            q[j + 2] = v.z * 0.125f;
            q[j + 3] = v.w * 0.125f;
        }
    }

    float acc[H_];
    #pragma unroll
    for (int j = 0; j < H_; ++j) acc[j] = 0.f;
    float m = -1e30f;
    float l = 0.f;

    for (int s = 0; s <= t; ++s) {
        const float4* k4 = reinterpret_cast<const float4*>(&Ks[s * H_]);
        float w0 = 0.f, w1 = 0.f, w2 = 0.f, w3 = 0.f;
        #pragma unroll
        for (int j4 = 0; j4 < 16; ++j4) {
            float4 kk = k4[j4];
            w0 += q[4 * j4 + 0] * kk.x;
            w1 += q[4 * j4 + 1] * kk.y;
            w2 += q[4 * j4 + 2] * kk.z;
            w3 += q[4 * j4 + 3] * kk.w;
        }
        const float w = (w0 + w1) + (w2 + w3);

        const float4* v4 = reinterpret_cast<const float4*>(&Vs[s * H_]);
        if (w <= m) {
            const float p = __expf(w - m);
            l += p;
            #pragma unroll
            for (int j4 = 0; j4 < 16; ++j4) {
                float4 vv = v4[j4];
                acc[4 * j4 + 0] += p * vv.x;
                acc[4 * j4 + 1] += p * vv.y;
                acc[4 * j4 + 2] += p * vv.z;
                acc[4 * j4 + 3] += p * vv.w;
            }
        } else {
            const float c = __expf(m - w);
            l = l * c + 1.f;
            #pragma unroll
            for (int j4 = 0; j4 < 16; ++j4) {
                float4 vv = v4[j4];
                acc[4 * j4 + 0] = acc[4 * j4 + 0] * c + vv.x;
                acc[4 * j4 + 1] = acc[4 * j4 + 1] * c + vv.y;
                acc[4 * j4 + 2] = acc[4 * j4 + 2] * c + vv.z;
                acc[4 * j4 + 3] = acc[4 * j4 + 3] * c + vv.w;
            }
            m = w;
        }
    }

    const float inv = 1.f / l;
    float* op = out + ((size_t)b * T_ + t) * H_;
    #pragma unroll
    for (int j = 0; j < H_; j += 4) {
        float4 o;
        o.x = acc[j + 0] * inv;
        o.y = acc[j + 1] * inv;
        o.z = acc[j + 2] * inv;
        o.w = acc[j + 3] * inv;
        *reinterpret_cast<float4*>(&op[j]) = o;
    }
}

// ---------------------------------------------------------------------------
extern "C" void kernel_launch(void* const* d_in, const int* in_sizes, int n_in,
                              void* d_out, int out_size)
{
    const float* x  = (const float*)d_in[0];
    const float* Wq = (const float*)d_in[1];
    const float* Wk = (const float*)d_in[2];
    const float* Wv = (const float*)d_in[3];
    float* out = (float*)d_out;

    cudaFuncSetAttribute(proj_kernel,
                         cudaFuncAttributeMaxDynamicSharedMemorySize, PROJ_SMEM);
    cudaFuncSetAttribute(attn_kernel,
                         cudaFuncAttributeMaxDynamicSharedMemorySize,
                         2 * T_ * H_ * (int)sizeof(float));

    wconv_kernel<<<384, 256>>>(Wq, Wk, Wv);
    proj_kernel<<<M_ / 128, 384, PROJ_SMEM>>>(x);
    attn_kernel<<<B_, 256, 2 * T_ * H_ * (int)sizeof(float)>>>(out);
}

// round 17
// speedup vs baseline: 2.4965x; 1.4785x over previous
#include <cuda_runtime.h>
#include <cuda_bf16.h>
#include <cstdint>

// Problem: single-head causal attention
//   x [1024,256,512] fp32, Wq/Wk/Wv [512,64] fp32 -> out [1024,256,64] fp32
#define B_ 1024
#define T_ 256
#define C_ 512
#define H_ 64
#define M_ (B_ * T_)

// Scratch for Q, K, V.
__device__ float g_q[(size_t)M_ * H_];
__device__ float g_k[(size_t)M_ * H_];
__device__ float g_v[(size_t)M_ * H_];

// Pre-converted, transposed weights: [o][n=64][k=512] bf16, hi/lo split.
__device__ __align__(16) __nv_bfloat16 g_wt_hi[3 * H_ * C_];
__device__ __align__(16) __nv_bfloat16 g_wt_lo[3 * H_ * C_];

// ---------------------------------------------------------------------------
// PTX helpers (sm_80-class features only: ldmatrix, mma.sync, cp.async).
// ---------------------------------------------------------------------------
__device__ __forceinline__ uint32_t smem_u32(const void* p) {
    uint32_t a;
    asm("{ .reg .u64 t; cvta.to.shared.u64 t, %1; cvt.u32.u64 %0, t; }"
        : "=r"(a) : "l"(p));
    return a;
}
__device__ __forceinline__ void ldsm_x4(uint32_t addr, uint32_t r[4]) {
    asm volatile("ldmatrix.sync.aligned.m8n8.x4.shared.b16 {%0,%1,%2,%3}, [%4];"
                 : "=r"(r[0]), "=r"(r[1]), "=r"(r[2]), "=r"(r[3]) : "r"(addr));
}
__device__ __forceinline__ void ldsm_x4_t(uint32_t addr, uint32_t r[4]) {
    asm volatile("ldmatrix.sync.aligned.m8n8.x4.trans.shared.b16 {%0,%1,%2,%3}, [%4];"
                 : "=r"(r[0]), "=r"(r[1]), "=r"(r[2]), "=r"(r[3]) : "r"(addr));
}
__device__ __forceinline__ void mma_bf16(float c[4], const uint32_t a[4],
                                         uint32_t b0, uint32_t b1) {
    asm volatile(
        "mma.sync.aligned.m16n8k16.row.col.f32.bf16.bf16.f32 "
        "{%0,%1,%2,%3}, {%4,%5,%6,%7}, {%8,%9}, {%0,%1,%2,%3};"
        : "+f"(c[0]), "+f"(c[1]), "+f"(c[2]), "+f"(c[3])
        : "r"(a[0]), "r"(a[1]), "r"(a[2]), "r"(a[3]), "r"(b0), "r"(b1));
}
__device__ __forceinline__ void cp16(uint32_t dst, const void* src) {
    asm volatile("cp.async.ca.shared.global [%0], [%1], 16;"
                 :: "r"(dst), "l"(src) : "memory");
}
#define CP_COMMIT() asm volatile("cp.async.commit_group;" ::: "memory")
#define CP_WAIT0()  asm volatile("cp.async.wait_group 0;" ::: "memory")

__device__ __forceinline__ uint32_t pack_bf16x2(float a, float b) {
    __nv_bfloat16 ha = __float2bfloat16(a);
    __nv_bfloat16 hb = __float2bfloat16(b);
    return ((uint32_t)__bfloat16_as_ushort(hb) << 16) | __bfloat16_as_ushort(ha);
}
__device__ __forceinline__ void split2(float2 v, uint32_t& hi, uint32_t& lo) {
    __nv_bfloat16 h0 = __float2bfloat16(v.x);
    __nv_bfloat16 h1 = __float2bfloat16(v.y);
    hi = ((uint32_t)__bfloat16_as_ushort(h1) << 16) | __bfloat16_as_ushort(h0);
    lo = pack_bf16x2(v.x - __bfloat162float(h0), v.y - __bfloat162float(h1));
}

// ---------------------------------------------------------------------------
// Kernel 0: one-time W convert+transpose+split (k fastest -> coalesced).
// ---------------------------------------------------------------------------
__global__ void wconv_kernel(const float* __restrict__ Wq,
                             const float* __restrict__ Wk,
                             const float* __restrict__ Wv)
{
    const int id = blockIdx.x * 256 + threadIdx.x;   // < 98304
    const int o   = id >> 15;
    const int rem = id & 32767;
    const int n   = rem >> 9;
    const int k   = rem & 511;
    const float* W = (o == 0) ? Wq : (o == 1) ? Wk : Wv;
    const float v = W[(size_t)k * H_ + n];
    const __nv_bfloat16 h = __float2bfloat16(v);
    g_wt_hi[id] = h;
    g_wt_lo[id] = __float2bfloat16(v - __bfloat162float(h));
}

// ---------------------------------------------------------------------------
// Kernel 1: QKV projection on HMMA, software-pipelined (unchanged from R12).
// ---------------------------------------------------------------------------
#define ROWB    144
#define SM_A_HI 0
#define SM_A_LO 18432
#define SM_B    36864
#define BBUF    55296
#define PROJ_SMEM (36864 + 2 * 55296)

__global__ __launch_bounds__(384, 1)
void proj_kernel(const float* __restrict__ X)
{
    extern __shared__ __align__(16) char smem[];
    const uint32_t sb = smem_u32(smem);
    const int tid  = threadIdx.x;
    const int lane = tid & 31;
    const int wid  = tid >> 5;
    const int row0 = blockIdx.x * 128;

    const int o  = wid >> 2;
    const int m0 = (wid & 3) * 32;

    float acc[2][8][4];
    #pragma unroll
    for (int mt = 0; mt < 2; ++mt)
        #pragma unroll
        for (int nt = 0; nt < 8; ++nt)
            #pragma unroll
            for (int i = 0; i < 4; ++i) acc[mt][nt][i] = 0.f;

    const int lr = lane & 7;
    const int ls = lane >> 3;
    const uint32_t kpart = (uint32_t)((ls >> 1) << 4);
    uint32_t a_off[2], b_off[4];
    #pragma unroll
    for (int mt = 0; mt < 2; ++mt)
        a_off[mt] = (uint32_t)(m0 + mt * 16 + lr + ((ls & 1) << 3)) * ROWB + kpart;
    #pragma unroll
    for (int np = 0; np < 4; ++np)
        b_off[np] = (uint32_t)(np * 16 + lr + ((ls & 1) << 3)) * ROWB + kpart;

    const uint32_t aHi = sb + SM_A_HI;
    const uint32_t aLo = sb + SM_A_LO;

    float4 xa[6];
    auto ldg_x = [&](int k0) {
        #pragma unroll
        for (int it = 0; it < 6; ++it) {
            const int id = tid + it * 384;
            if (id < 2048) {
                const int r  = id >> 4;
                const int c4 = (id & 15) * 4;
                xa[it] = *reinterpret_cast<const float4*>(
                    &X[(size_t)(row0 + r) * C_ + k0 + c4]);
            }
        }
    };
    auto cp_b = [&](int k0, int buf) {
        const uint32_t dst0 = sb + SM_B + (uint32_t)buf * BBUF;
        #pragma unroll
        for (int it = 0; it < 8; ++it) {
            const int id  = tid + it * 384;
            const int o2  = id >> 9;
            const int rem = id & 511;
            const int r   = rem >> 3;
            const int j   = rem & 7;
            const __nv_bfloat16* src = ((o2 & 1) ? g_wt_lo : g_wt_hi) +
                (size_t)(o2 >> 1) * 32768 + (size_t)r * 512 + k0 + j * 8;
            cp16(dst0 + (uint32_t)o2 * 9216 + (uint32_t)r * ROWB + j * 16, src);
        }
        CP_COMMIT();
    };

    ldg_x(0);
    cp_b(0, 0);

    for (int ch = 0; ch < 8; ++ch) {
        CP_WAIT0();
        __syncthreads();

        #pragma unroll
        for (int it = 0; it < 6; ++it) {
            const int id = tid + it * 384;
            if (id < 2048) {
                const int r  = id >> 4;
                const int c4 = (id & 15) * 4;
                const uint32_t d = (uint32_t)r * ROWB + (uint32_t)c4 * 2;
                uint32_t h01, l01, h23, l23;
                split2(make_float2(xa[it].x, xa[it].y), h01, l01);
                split2(make_float2(xa[it].z, xa[it].w), h23, l23);
                *reinterpret_cast<uint32_t*>(smem + SM_A_HI + d)     = h01;
                *reinterpret_cast<uint32_t*>(smem + SM_A_HI + d + 4) = h23;
                *reinterpret_cast<uint32_t*>(smem + SM_A_LO + d)     = l01;
                *reinterpret_cast<uint32_t*>(smem + SM_A_LO + d + 4) = l23;
            }
        }
        if (ch < 7) {
            ldg_x((ch + 1) * 64);
            cp_b((ch + 1) * 64, (ch + 1) & 1);
        }
        __syncthreads();

        const uint32_t bHi = sb + SM_B + (uint32_t)(ch & 1) * BBUF +
                             (uint32_t)(o * 2 + 0) * 9216;
        const uint32_t bLo = bHi + 9216;

        #pragma unroll
        for (int s = 0; s < 4; ++s) {
            const uint32_t kb = (uint32_t)s * 32;
            uint32_t ah[2][4], al[2][4], bh[4][4], bl[4][4];
            ldsm_x4(aHi + a_off[0] + kb, ah[0]);
            ldsm_x4(aHi + a_off[1] + kb, ah[1]);
            ldsm_x4(aLo + a_off[0] + kb, al[0]);
            ldsm_x4(aLo + a_off[1] + kb, al[1]);
            #pragma unroll
            for (int np = 0; np < 4; ++np) {
                ldsm_x4(bHi + b_off[np] + kb, bh[np]);
                ldsm_x4(bLo + b_off[np] + kb, bl[np]);
            }
            #pragma unroll
            for (int mt = 0; mt < 2; ++mt)
                #pragma unroll
                for (int nt = 0; nt < 8; ++nt)
                    mma_bf16(acc[mt][nt], ah[mt],
                             bh[nt >> 1][nt & 1], bh[nt >> 1][2 + (nt & 1)]);
            #pragma unroll
            for (int mt = 0; mt < 2; ++mt)
                #pragma unroll
                for (int nt = 0; nt < 8; ++nt)
                    mma_bf16(acc[mt][nt], ah[mt],
                             bl[nt >> 1][nt & 1], bl[nt >> 1][2 + (nt & 1)]);
            #pragma unroll
            for (int mt = 0; mt < 2; ++mt)
                #pragma unroll
                for (int nt = 0; nt < 8; ++nt)
                    mma_bf16(acc[mt][nt], al[mt],
                             bh[nt >> 1][nt & 1], bh[nt >> 1][2 + (nt & 1)]);
        }
    }

    const int g  = lane >> 2;
    const int tg = lane & 3;
    float* dst = (o == 0) ? g_q : (o == 1) ? g_k : g_v;
    #pragma unroll
    for (int mt = 0; mt < 2; ++mt) {
        #pragma unroll
        for (int nt = 0; nt < 8; ++nt) {
            const int row = row0 + m0 + mt * 16 + g;
            const int col = nt * 8 + tg * 2;
            float2 lo2 = make_float2(acc[mt][nt][0], acc[mt][nt][1]);
            float2 hi2 = make_float2(acc[mt][nt][2], acc[mt][nt][3]);
            *reinterpret_cast<float2*>(&dst[(size_t)row * H_ + col])       = lo2;
            *reinterpret_cast<float2*>(&dst[(size_t)(row + 8) * H_ + col]) = hi2;
        }
    }
}

// ---------------------------------------------------------------------------
// Kernel 2: causal flash attention on HMMA (bf16 hi/lo 3-pass for both GEMMs).
// One CTA per batch; Q(scaled)/K/V staged as bf16 hi/lo in smem (144B rows).
// 8 warps x 32 query rows, causal-balanced rb = (w<4 ? w : 11-w).
// Per 64-col s-block: QK^T mma -> mask -> register softmax (4-lane shfls)
// -> P repack (C-tile pair == A-frag) -> P@V with V B-frags via ldmatrix.trans.
// ---------------------------------------------------------------------------
#define A_QH 0
#define A_QL 36864
#define A_KH 73728
#define A_KL 110592
#define A_VH 147456
#define A_VL 184320
#define ATTN_SMEM 221184

__global__ __launch_bounds__(256, 1)
void attn_kernel(float* __restrict__ out)
{
    extern __shared__ __align__(16) char smem[];
    const uint32_t sb = smem_u32(smem);
    const int b    = blockIdx.x;
    const int tid  = threadIdx.x;
    const int lane = tid & 31;
    const int wid  = tid >> 5;

    // ---- stage Q(*0.125)/K/V fp32 -> bf16 hi/lo smem ----
    #pragma unroll
    for (int arr = 0; arr < 3; ++arr) {
        const float* src = ((arr == 0) ? g_q : (arr == 1) ? g_k : g_v) +
                           (size_t)b * T_ * H_;
        const uint32_t dh = (arr == 0) ? A_QH : (arr == 1) ? A_KH : A_VH;
        const uint32_t dl = dh + 36864;
        for (int i = tid; i < 4096; i += 256) {
            const int r  = i >> 4;
            const int c4 = (i & 15) * 4;
            float4 v = reinterpret_cast<const float4*>(src)[i];
            if (arr == 0) { v.x *= 0.125f; v.y *= 0.125f; v.z *= 0.125f; v.w *= 0.125f; }
            const uint32_t d = (uint32_t)r * ROWB + (uint32_t)c4 * 2;
            uint32_t h01, l01, h23, l23;
            split2(make_float2(v.x, v.y), h01, l01);
            split2(make_float2(v.z, v.w), h23, l23);
            *reinterpret_cast<uint32_t*>(smem + dh + d)     = h01;
            *reinterpret_cast<uint32_t*>(smem + dh + d + 4) = h23;
            *reinterpret_cast<uint32_t*>(smem + dl + d)     = l01;
            *reinterpret_cast<uint32_t*>(smem + dl + d + 4) = l23;
        }
    }
    __syncthreads();

    const int rb = (wid < 4) ? wid : (11 - wid);   // causal-balanced row block

    // ldmatrix lane mapping (non-trans; proven in proj)
    const int lr = lane & 7;
    const int ls = lane >> 3;
    const uint32_t kpart = (uint32_t)((ls >> 1) << 4);
    uint32_t qa_off[2], kb_off[4];
    #pragma unroll
    for (int mt = 0; mt < 2; ++mt)
        qa_off[mt] = (uint32_t)(rb * 32 + mt * 16 + lr + ((ls & 1) << 3)) * ROWB + kpart;
    #pragma unroll
    for (int np = 0; np < 4; ++np)
        kb_off[np] = (uint32_t)(np * 16 + lr + ((ls & 1) << 3)) * ROWB + kpart;
    // trans lane mapping for V (k=s rows, n=h cols)
    const uint32_t v_off = (uint32_t)((lane & 7) + 8 * ((lane >> 3) & 1)) * ROWB +
                           (uint32_t)(lane >> 4) * 16;

    // Q A-fragments: hi persistent in regs, lo reloaded per block
    uint32_t qh[2][4][4];
    #pragma unroll
    for (int mt = 0; mt < 2; ++mt)
        #pragma unroll
        for (int ks = 0; ks < 4; ++ks)
            ldsm_x4(sb + A_QH + qa_off[mt] + ks * 32, qh[mt][ks]);

    float oacc[2][8][4];
    #pragma unroll
    for (int mt = 0; mt < 2; ++mt)
        #pragma unroll
        for (int nt = 0; nt < 8; ++nt)
            #pragma unroll
            for (int i = 0; i < 4; ++i) oacc[mt][nt][i] = 0.f;
    float mrow[2][2], lrow[2][2];
    #pragma unroll
    for (int mt = 0; mt < 2; ++mt) {
        mrow[mt][0] = mrow[mt][1] = -1e30f;
        lrow[mt][0] = lrow[mt][1] = 0.f;
    }

    const int nblocks = (rb >> 1) + 1;
    for (int nb = 0; nb < nblocks; ++nb) {
        float S[2][8][4];
        #pragma unroll
        for (int mt = 0; mt < 2; ++mt)
            #pragma unroll
            for (int nt = 0; nt < 8; ++nt)
                #pragma unroll
                for (int i = 0; i < 4; ++i) S[mt][nt][i] = 0.f;

        // ---- QK^T: S[32, 64] over c=64, 3 passes ----
        const uint32_t kH = sb + A_KH + (uint32_t)nb * 64 * ROWB;
        const uint32_t kL = sb + A_KL + (uint32_t)nb * 64 * ROWB;
        #pragma unroll
        for (int ks = 0; ks < 4; ++ks) {
            const uint32_t kb = (uint32_t)ks * 32;
            uint32_t bh[4][4], bl[4][4], ql[2][4];
            #pragma unroll
            for (int np = 0; np < 4; ++np) {
                ldsm_x4(kH + kb_off[np] + kb, bh[np]);
                ldsm_x4(kL + kb_off[np] + kb, bl[np]);
            }
            ldsm_x4(sb + A_QL + qa_off[0] + kb, ql[0]);
            ldsm_x4(sb + A_QL + qa_off[1] + kb, ql[1]);
            #pragma unroll
            for (int mt = 0; mt < 2; ++mt)
                #pragma unroll
                for (int nt = 0; nt < 8; ++nt)
                    mma_bf16(S[mt][nt], qh[mt][ks],
                             bh[nt >> 1][nt & 1], bh[nt >> 1][2 + (nt & 1)]);
            #pragma unroll
            for (int mt = 0; mt < 2; ++mt)
                #pragma unroll
                for (int nt = 0; nt < 8; ++nt)
                    mma_bf16(S[mt][nt], qh[mt][ks],
                             bl[nt >> 1][nt & 1], bl[nt >> 1][2 + (nt & 1)]);
            #pragma unroll
            for (int mt = 0; mt < 2; ++mt)
                #pragma unroll
                for (int nt = 0; nt < 8; ++nt)
                    mma_bf16(S[mt][nt], ql[mt],
                             bh[nt >> 1][nt & 1], bh[nt >> 1][2 + (nt & 1)]);
        }

        // ---- causal mask on diagonal block ----
        if (nb == (rb >> 1)) {
            #pragma unroll
            for (int mt = 0; mt < 2; ++mt)
                #pragma unroll
                for (int nt = 0; nt < 8; ++nt)
                    #pragma unroll
                    for (int j = 0; j < 4; ++j) {
                        const int col = nb * 64 + nt * 8 + (lane & 3) * 2 + (j & 1);
                        const int row = rb * 32 + mt * 16 + (lane >> 2) + ((j >> 1) * 8);
                        if (col > row) S[mt][nt][j] = -1e30f;
                    }
        }

        // ---- online softmax (rows r and r+8 per mt; 4-lane tg groups) ----
        #pragma unroll
        for (int mt = 0; mt < 2; ++mt) {
            float bm0 = -1e30f, bm1 = -1e30f;
            #pragma unroll
            for (int nt = 0; nt < 8; ++nt) {
                bm0 = fmaxf(bm0, fmaxf(S[mt][nt][0], S[mt][nt][1]));
                bm1 = fmaxf(bm1, fmaxf(S[mt][nt][2], S[mt][nt][3]));
            }
            bm0 = fmaxf(bm0, __shfl_xor_sync(0xFFFFFFFFu, bm0, 1));
            bm0 = fmaxf(bm0, __shfl_xor_sync(0xFFFFFFFFu, bm0, 2));
            bm1 = fmaxf(bm1, __shfl_xor_sync(0xFFFFFFFFu, bm1, 1));
            bm1 = fmaxf(bm1, __shfl_xor_sync(0xFFFFFFFFu, bm1, 2));
            const float nm0 = fmaxf(mrow[mt][0], bm0);
            const float nm1 = fmaxf(mrow[mt][1], bm1);
            const float c0 = __expf(mrow[mt][0] - nm0);
            const float c1 = __expf(mrow[mt][1] - nm1);
            mrow[mt][0] = nm0;
            mrow[mt][1] = nm1;
            float rs0 = 0.f, rs1 = 0.f;
            #pragma unroll
            for (int nt = 0; nt < 8; ++nt) {
                S[mt][nt][0] = __expf(S[mt][nt][0] - nm0);
                S[mt][nt][1] = __expf(S[mt][nt][1] - nm0);
                S[mt][nt][2] = __expf(S[mt][nt][2] - nm1);
                S[mt][nt][3] = __expf(S[mt][nt][3] - nm1);
                rs0 += S[mt][nt][0] + S[mt][nt][1];
                rs1 += S[mt][nt][2] + S[mt][nt][3];
            }
            rs0 += __shfl_xor_sync(0xFFFFFFFFu, rs0, 1);
            rs0 += __shfl_xor_sync(0xFFFFFFFFu, rs0, 2);
            rs1 += __shfl_xor_sync(0xFFFFFFFFu, rs1, 1);
            rs1 += __shfl_xor_sync(0xFFFFFFFFu, rs1, 2);
            lrow[mt][0] = lrow[mt][0] * c0 + rs0;
            lrow[mt][1] = lrow[mt][1] * c1 + rs1;
            #pragma unroll
            for (int nt = 0; nt < 8; ++nt) {
                oacc[mt][nt][0] *= c0;
                oacc[mt][nt][1] *= c0;
                oacc[mt][nt][2] *= c1;
                oacc[mt][nt][3] *= c1;
            }
        }

        // ---- P@V: K-dim = 64 s, 4 ks steps; P hi/lo from S regs ----
        const uint32_t vH = sb + A_VH + (uint32_t)nb * 64 * ROWB + v_off;
        const uint32_t vL = sb + A_VL + (uint32_t)nb * 64 * ROWB + v_off;
        #pragma unroll
        for (int ks = 0; ks < 4; ++ks) {
            uint32_t ph[2][4], pl[2][4];
            #pragma unroll
            for (int mt = 0; mt < 2; ++mt) {
                split2(make_float2(S[mt][2 * ks][0],     S[mt][2 * ks][1]),     ph[mt][0], pl[mt][0]);
                split2(make_float2(S[mt][2 * ks][2],     S[mt][2 * ks][3]),     ph[mt][1], pl[mt][1]);
                split2(make_float2(S[mt][2 * ks + 1][0], S[mt][2 * ks + 1][1]), ph[mt][2], pl[mt][2]);
                split2(make_float2(S[mt][2 * ks + 1][2], S[mt][2 * ks + 1][3]), ph[mt][3], pl[mt][3]);
            }
            uint32_t vh[4][4], vl[4][4];
            #pragma unroll
            for (int c = 0; c < 4; ++c) {
                ldsm_x4_t(vH + (uint32_t)ks * 16 * ROWB + c * 32, vh[c]);
                ldsm_x4_t(vL + (uint32_t)ks * 16 * ROWB + c * 32, vl[c]);
            }
            #pragma unroll
            for (int mt = 0; mt < 2; ++mt)
                #pragma unroll
                for (int nt = 0; nt < 8; ++nt)
                    mma_bf16(oacc[mt][nt], ph[mt],
                             vh[nt >> 1][(nt & 1) * 2], vh[nt >> 1][(nt & 1) * 2 + 1]);
            #pragma unroll
            for (int mt = 0; mt < 2; ++mt)
                #pragma unroll
                for (int nt = 0; nt < 8; ++nt)
                    mma_bf16(oacc[mt][nt], ph[mt],
                             vl[nt >> 1][(nt & 1) * 2], vl[nt >> 1][(nt & 1) * 2 + 1]);
            #pragma unroll
            for (int mt = 0; mt < 2; ++mt)
                #pragma unroll
                for (int nt = 0; nt < 8; ++nt)
                    mma_bf16(oacc[mt][nt], pl[mt],
                             vh[nt >> 1][(nt & 1) * 2], vh[nt >> 1][(nt & 1) * 2 + 1]);
        }
    }

    // ---- epilogue: /l, write fp32 ----
    const int g  = lane >> 2;
    const int tg = lane & 3;
    #pragma unroll
    for (int mt = 0; mt < 2; ++mt) {
        const float inv0 = 1.f / lrow[mt][0];
        const float inv1 = 1.f / lrow[mt][1];
        const int r0 = rb * 32 + mt * 16 + g;
        #pragma unroll
        for (int nt = 0; nt < 8; ++nt) {
            const int col = nt * 8 + tg * 2;
            *reinterpret_cast<float2*>(&out[((size_t)b * T_ + r0) * H_ + col]) =
                make_float2(oacc[mt][nt][0] * inv0, oacc[mt][nt][1] * inv0);
            *reinterpret_cast<float2*>(&out[((size_t)b * T_ + r0 + 8) * H_ + col]) =
                make_float2(oacc[mt][nt][2] * inv1, oacc[mt][nt][3] * inv1);
        }
    }
}

// ---------------------------------------------------------------------------
extern "C" void kernel_launch(void* const* d_in, const int* in_sizes, int n_in,
                              void* d_out, int out_size)
{
    const float* x  = (const float*)d_in[0];
    const float* Wq = (const float*)d_in[1];
    const float* Wk = (const float*)d_in[2];
    const float* Wv = (const float*)d_in[3];
    float* out = (float*)d_out;

    cudaFuncSetAttribute(proj_kernel,
                         cudaFuncAttributeMaxDynamicSharedMemorySize, PROJ_SMEM);
    cudaFuncSetAttribute(attn_kernel,
                         cudaFuncAttributeMaxDynamicSharedMemorySize, ATTN_SMEM);

    wconv_kernel<<<384, 256>>>(Wq, Wk, Wv);
    proj_kernel<<<M_ / 128, 384, PROJ_SMEM>>>(x);
    attn_kernel<<<B_, 256, ATTN_SMEM>>>(out);
}